// round 3
// baseline (speedup 1.0000x reference)
#include <cuda_runtime.h>
#include <cstdint>

#define B_ 8
#define N_ 256
#define L_ 48
#define F_ 96
#define LF (L_*F_)
#define XS 260    // padded position stride (floats) for [l][pos] smem x tiles
#define WDL 112   // ull per l-row of duplicated-w smem (8 fg-slots * 14 ull, conflict-free)

typedef unsigned long long ull;

// ---------------- scratch (no allocation allowed) ----------------
__device__ float g_rowsum [B_*N_*L_];
__device__ float g_diag   [B_*N_*L_];
__device__ float g_colpart[B_*16*N_*L_];   // per-i-strip colsum partials
__device__ float g_stripT [B_*16*L_];      // per-strip trace partials
__device__ float g_stripS [B_*16*L_];      // per-strip totsum partials
__device__ float g_diagA  [B_*N_*F_];
__device__ float g_bi     [B_*N_*F_];
__device__ float g_bjs    [B_*N_*F_];

// ---------------- f32x2 helpers ----------------
__device__ __forceinline__ ull pk2(float a){
    ull r; asm("mov.b64 %0, {%1,%1};" : "=l"(r) : "f"(a)); return r;
}
__device__ __forceinline__ ull ffma2(ull a, ull b, ull c){
    ull d; asm("fma.rn.f32x2 %0, %1, %2, %3;" : "=l"(d) : "l"(a), "l"(b), "l"(c)); return d;
}
__device__ __forceinline__ void upk(ull v, float &a, float &b){
    asm("mov.b64 {%0,%1}, %2;" : "=f"(a), "=f"(b) : "l"(v));
}

// ================= K0: fused reductions, one pass over x =================
// grid (16 istrips, B). block 384: q = t/12 (0..31 j-groups), lq = (t%12)*4.
// Computes: rowsum[b,i,:], diag[b,i,:], colpart[b,strip,j,:], strip trace/totsum.
__global__ __launch_bounds__(384) void k_reduce(const float* __restrict__ x){
    const int istrip = blockIdx.x, b = blockIdx.y;
    const int i0 = istrip*16;
    const int t = threadIdx.x;
    const int q = t/12, lq = (t%12)*4;

    __shared__ float rp[32][48];
    __shared__ float tracc[48], tsacc[48];
    if (t < 48){ tracc[t] = 0.f; tsacc[t] = 0.f; }

    float ca[8][4];
    #pragma unroll
    for (int jj = 0; jj < 8; jj++){ ca[jj][0]=0.f; ca[jj][1]=0.f; ca[jj][2]=0.f; ca[jj][3]=0.f; }

    const float* xb = x + ((size_t)b)*N_*N_*L_;

    for (int ii = 0; ii < 16; ii++){
        const int i = i0 + ii;
        const float* xr = xb + (size_t)i*N_*L_;
        float r0=0.f, r1=0.f, r2=0.f, r3=0.f;
        #pragma unroll
        for (int jj = 0; jj < 8; jj++){
            const int j = q + 32*jj;
            float4 v = *(const float4*)(xr + j*L_ + lq);
            ca[jj][0]+=v.x; ca[jj][1]+=v.y; ca[jj][2]+=v.z; ca[jj][3]+=v.w;
            r0+=v.x; r1+=v.y; r2+=v.z; r3+=v.w;
        }
        __syncthreads();
        rp[q][lq+0]=r0; rp[q][lq+1]=r1; rp[q][lq+2]=r2; rp[q][lq+3]=r3;
        __syncthreads();
        if (t < 48){
            float s = 0.f;
            #pragma unroll 8
            for (int qq = 0; qq < 32; qq++) s += rp[qq][t];
            g_rowsum[(b*N_+i)*L_ + t] = s;
            tsacc[t] += s;
            const float dv = xr[(size_t)i*L_ + t];
            g_diag[(b*N_+i)*L_ + t] = dv;
            tracc[t] += dv;
        }
    }
    __syncthreads();
    // write colsum partials
    #pragma unroll
    for (int jj = 0; jj < 8; jj++){
        const int j = q + 32*jj;
        float* cp = g_colpart + ((size_t)((b*16+istrip)*N_ + j))*L_ + lq;
        cp[0]=ca[jj][0]; cp[1]=ca[jj][1]; cp[2]=ca[jj][2]; cp[3]=ca[jj][3];
    }
    if (t < 48){
        g_stripT[(b*16+istrip)*L_ + t] = tracc[t];
        g_stripS[(b*16+istrip)*L_ + t] = tsacc[t];
    }
}

// ================= K1: per-node projections (8 nodes/block) + scalars =================
// grid (32 chunks, B), 96 threads (t = feature f).
__global__ __launch_bounds__(96) void k_node(const float* __restrict__ w){
    const int b = blockIdx.y;
    const int n0 = blockIdx.x * 8;
    const int t = threadIdx.x;

    __shared__ float d_[8][48], r_[8][48], c_[8][48];
    __shared__ float tr[48], ts[48];

    // load diag/rowsum and reduce colsum partials
    for (int idx = t; idx < 8*48; idx += 96){
        const int nn = idx / 48, l = idx % 48;
        const int base = (b*N_ + n0 + nn)*L_ + l;
        d_[nn][l] = g_diag  [base];
        r_[nn][l] = g_rowsum[base];
        float s = 0.f;
        #pragma unroll
        for (int st = 0; st < 16; st++)
            s += g_colpart[((size_t)((b*16+st)*N_ + n0 + nn))*L_ + l];
        c_[nn][l] = s;
    }
    if (t < 48){
        float a = 0.f, s = 0.f;
        #pragma unroll
        for (int st = 0; st < 16; st++){
            a += g_stripT[(b*16+st)*L_ + t];
            s += g_stripS[(b*16+st)*L_ + t];
        }
        tr[t] = a; ts[t] = s;
    }
    __syncthreads();

    float aA[8], aJ[8], aI[8];
    #pragma unroll
    for (int nn = 0; nn < 8; nn++){ aA[nn]=0.f; aJ[nn]=0.f; aI[nn]=0.f; }
    float ds = 0.f, sc = 0.f;

    for (int l = 0; l < 48; l++){
        const float* wl = w + l*F_ + t;
        const float w0  = __ldg(wl);
        const float w1  = __ldg(wl +    LF);
        const float w2  = __ldg(wl +  2*LF);
        const float w3  = __ldg(wl +  3*LF);
        const float w4  = __ldg(wl +  4*LF);
        const float w5  = __ldg(wl +  5*LF);
        const float w6  = __ldg(wl +  6*LF);
        const float w7  = __ldg(wl +  7*LF);
        const float w8  = __ldg(wl +  8*LF);
        const float w9  = __ldg(wl +  9*LF);
        const float w10 = __ldg(wl + 10*LF);
        const float w13 = __ldg(wl + 13*LF);
        const float w14 = __ldg(wl + 14*LF);
        const float trl = tr[l], tsl = ts[l];
        ds += trl*w3  + tsl*w4;
        sc += trl*w13 + tsl*w14;
        #pragma unroll
        for (int nn = 0; nn < 8; nn++){
            const float dd = d_[nn][l], rr = r_[nn][l], cc = c_[nn][l];
            aA[nn] += dd*w0 + rr*w1 + cc*w2;
            aJ[nn] += dd*w5 + rr*w6 + cc*w7;
            aI[nn] += dd*w8 + rr*w9 + cc*w10;
        }
    }
    #pragma unroll
    for (int nn = 0; nn < 8; nn++){
        const int o = (b*N_ + n0 + nn)*F_ + t;
        g_diagA[o] = aA[nn] + ds;
        g_bjs  [o] = aJ[nn] + sc;
        g_bi   [o] = aI[nn];
    }
}

// ================= K2: main fused kernel =================
// 16x16 (i,j) tile, 512 threads. Position-pair FFMA2 packing:
//   acc pairs two adjacent j positions; x pairs come free from ulonglong2 smem
//   loads; w is pre-duplicated in smem ({w,w} ulls, 14-ull fg stride).
__global__ __launch_bounds__(512, 1)
void k_main(const float* __restrict__ x, const float* __restrict__ w,
            float* __restrict__ out){
    const int jt = blockIdx.x, it = blockIdx.y, b = blockIdx.z;
    const int i0 = it*16, j0 = jt*16;
    const int tid = threadIdx.x;

    extern __shared__ float sm[];
    float* xd    = sm;                       // [48][XS]
    float* xt    = xd + 48*XS;               // [48][XS]
    ull*   wd12  = (ull*)(xt + 48*XS);       // [48][WDL]
    ull*   wd11  = wd12 + 48*WDL;            // [48][WDL]
    float* bis   = (float*)(wd11 + 48*WDL);  // [16][96]
    float* bjs_s = bis + 16*96;              // [16][96]

    // ---- stage duplicated w11/w12 ----
    const float* w11g = w + 11*LF;
    const float* w12g = w + 12*LF;
    for (int idx = tid; idx < LF; idx += 512){
        const int l = idx / 96, f = idx % 96;
        const int fgi = f / 12, fi = f % 12;
        const int dst = l*WDL + fgi*14 + fi;
        wd12[dst] = pk2(__ldg(w12g + idx));
        wd11[dst] = pk2(__ldg(w11g + idx));
    }
    // ---- stage bi / bjs tiles ----
    for (int idx = tid; idx < 16*F_; idx += 512){
        const int r = idx / F_, f = idx % F_;
        bis  [idx] = g_bi [(b*N_ + i0 + r)*F_ + f];
        bjs_s[idx] = g_bjs[(b*N_ + j0 + r)*F_ + f];
    }
    // ---- stage x tiles (direct + transposed), [l][pos] layout ----
    const float* xb = x + ((size_t)b)*N_*N_*L_;
    for (int idx4 = tid; idx4 < 3072; idx4 += 512){
        const int ti  = idx4 / 192;
        const int rem = idx4 % 192;
        const int tj  = rem / 12;
        const int l4  = (rem % 12)*4;
        float4 v = *(const float4*)(xb + (size_t)(i0+ti)*N_*L_ + (size_t)(j0+tj)*L_ + l4);
        const int p = ti*16 + tj;
        xd[(l4+0)*XS + p] = v.x; xd[(l4+1)*XS + p] = v.y;
        xd[(l4+2)*XS + p] = v.z; xd[(l4+3)*XS + p] = v.w;
    }
    for (int idx4 = tid; idx4 < 3072; idx4 += 512){
        const int tj  = idx4 / 192;
        const int rem = idx4 % 192;
        const int ti  = rem / 12;
        const int l4  = (rem % 12)*4;
        float4 v = *(const float4*)(xb + (size_t)(j0+tj)*N_*L_ + (size_t)(i0+ti)*L_ + l4);
        const int p = ti*16 + tj;
        xt[(l4+0)*XS + p] = v.x; xt[(l4+1)*XS + p] = v.y;
        xt[(l4+2)*XS + p] = v.z; xt[(l4+3)*XS + p] = v.w;
    }
    __syncthreads();

    // ---- compute: 4 positions x 12 features per thread ----
    const int fg  = tid & 7;          // 8 feature groups of 12
    const int pg  = tid >> 3;         // 64 groups of 4 positions
    const int f0  = fg * 12;
    const int ti  = pg >> 2;
    const int tjb = (pg & 3) * 4;
    const int p0  = ti*16 + tjb;

    ull acc[24];
    #pragma unroll
    for (int q = 0; q < 24; q++) acc[q] = 0ULL;

    const float* xdp = xd + p0;
    const float* xtp = xt + p0;
    const ull*   w2p = wd12 + fg*14;
    const ull*   w1p = wd11 + fg*14;

    #pragma unroll 2
    for (int l = 0; l < 48; l++){
        const ulonglong2 xa = *(const ulonglong2*)(xdp + l*XS);
        const ulonglong2 xc = *(const ulonglong2*)(xtp + l*XS);
        const ull* wr2 = w2p + l*WDL;
        const ull* wr1 = w1p + l*WDL;
        #pragma unroll
        for (int f = 0; f < 12; f++){
            const ull v2 = wr2[f];
            const ull v1 = wr1[f];
            acc[f]      = ffma2(xa.x, v2, acc[f]);
            acc[f]      = ffma2(xc.x, v1, acc[f]);
            acc[12 + f] = ffma2(xa.y, v2, acc[12 + f]);
            acc[12 + f] = ffma2(xc.y, v1, acc[12 + f]);
        }
    }

    // ---- epilogue ----
    const int gi = i0 + ti;
    float bic[12];
    {
        const float4* bp = (const float4*)(bis + ti*F_ + f0);
        float4 b0 = bp[0], b1 = bp[1], b2 = bp[2];
        bic[0]=b0.x; bic[1]=b0.y; bic[2]=b0.z; bic[3]=b0.w;
        bic[4]=b1.x; bic[5]=b1.y; bic[6]=b1.z; bic[7]=b1.w;
        bic[8]=b2.x; bic[9]=b2.y; bic[10]=b2.z; bic[11]=b2.w;
    }
    float* orow = out + (((size_t)(b*N_ + gi))*N_ + j0)*F_ + f0;

    #pragma unroll
    for (int pp = 0; pp < 4; pp++){
        const int tj = tjb + pp;
        const int pair = pp >> 1;
        float v[12];
        #pragma unroll
        for (int f = 0; f < 12; f++){
            float lo, hi;
            upk(acc[pair*12 + f], lo, hi);
            v[f] = (pp & 1) ? hi : lo;
        }
        const float* jp = bjs_s + tj*F_ + f0;
        #pragma unroll
        for (int f = 0; f < 12; f++) v[f] += bic[f] + jp[f];
        if (gi == j0 + tj){
            const float* dp = g_diagA + (size_t)(b*N_ + gi)*F_ + f0;
            #pragma unroll
            for (int f = 0; f < 12; f++) v[f] += __ldg(dp + f);
        }
        float* op = orow + (size_t)tj*F_;
        *(float4*)(op    ) = make_float4(v[0], v[1], v[2],  v[3]);
        *(float4*)(op + 4) = make_float4(v[4], v[5], v[6],  v[7]);
        *(float4*)(op + 8) = make_float4(v[8], v[9], v[10], v[11]);
    }
}

// ---------------- launch ----------------
extern "C" void kernel_launch(void* const* d_in, const int* in_sizes, int n_in,
                              void* d_out, int out_size){
    const float* x = (const float*)d_in[0];
    const float* w = (const float*)d_in[1];
    float* out = (float*)d_out;
    (void)in_sizes; (void)n_in; (void)out_size;

    k_reduce<<<dim3(16, B_), 384>>>(x);
    k_node  <<<dim3(32, B_), 96>>>(w);

    const size_t smem = (size_t)(2*48*XS)*sizeof(float)
                      + (size_t)(2*48*WDL)*sizeof(ull)
                      + (size_t)(2*16*96)*sizeof(float);   // 198144 B
    cudaFuncSetAttribute(k_main, cudaFuncAttributeMaxDynamicSharedMemorySize, (int)smem);
    k_main<<<dim3(16, 16, B_), 512, smem>>>(x, w, out);
}

// round 4
// speedup vs baseline: 1.1300x; 1.1300x over previous
#include <cuda_runtime.h>
#include <cstdint>

#define B_ 8
#define N_ 256
#define L_ 48
#define F_ 96
#define LF (L_*F_)
#define XS 260    // padded position stride (floats) for [l][pos] smem x tiles
#define NSTRIP 32 // i-strips for k_reduce (8 rows each)

typedef unsigned long long ull;

// ---------------- scratch (no allocation allowed) ----------------
__device__ float g_rowsum [B_*N_*L_];
__device__ float g_diag   [B_*N_*L_];
__device__ float g_colpart[B_*NSTRIP*N_*L_];   // per-i-strip colsum partials
__device__ float g_stripT [B_*NSTRIP*L_];      // per-strip trace partials
__device__ float g_stripS [B_*NSTRIP*L_];      // per-strip totsum partials
__device__ float g_diagA  [B_*N_*F_];
__device__ float g_bi     [B_*N_*F_];
__device__ float g_bjs    [B_*N_*F_];

// ---------------- f32x2 helpers ----------------
__device__ __forceinline__ ull pk2(float a){
    ull r; asm("mov.b64 %0, {%1,%1};" : "=l"(r) : "f"(a)); return r;
}
__device__ __forceinline__ ull ffma2(ull a, ull b, ull c){
    ull d; asm("fma.rn.f32x2 %0, %1, %2, %3;" : "=l"(d) : "l"(a), "l"(b), "l"(c)); return d;
}
__device__ __forceinline__ void upk(ull v, float &a, float &b){
    asm("mov.b64 {%0,%1}, %2;" : "=f"(a), "=f"(b) : "l"(v));
}

// ================= K0: fused reductions, one pass over x =================
// grid (NSTRIP, B), strips of 8 i-rows. block 384: q = t/12 (0..31 j-groups),
// lq = (t%12)*4. Computes rowsum, diag, colsum partials, strip trace/totsum.
__global__ __launch_bounds__(384) void k_reduce(const float* __restrict__ x){
    const int istrip = blockIdx.x, b = blockIdx.y;
    const int i0 = istrip*8;
    const int t = threadIdx.x;
    const int q = t/12, lq = (t%12)*4;

    __shared__ float rp[32][48];
    __shared__ float tracc[48], tsacc[48];
    if (t < 48){ tracc[t] = 0.f; tsacc[t] = 0.f; }

    float ca[8][4];
    #pragma unroll
    for (int jj = 0; jj < 8; jj++){ ca[jj][0]=0.f; ca[jj][1]=0.f; ca[jj][2]=0.f; ca[jj][3]=0.f; }

    const float* xb = x + ((size_t)b)*N_*N_*L_;

    for (int ii = 0; ii < 8; ii++){
        const int i = i0 + ii;
        const float* xr = xb + (size_t)i*N_*L_;
        float r0=0.f, r1=0.f, r2=0.f, r3=0.f;
        #pragma unroll
        for (int jj = 0; jj < 8; jj++){
            const int j = q + 32*jj;
            float4 v = *(const float4*)(xr + j*L_ + lq);
            ca[jj][0]+=v.x; ca[jj][1]+=v.y; ca[jj][2]+=v.z; ca[jj][3]+=v.w;
            r0+=v.x; r1+=v.y; r2+=v.z; r3+=v.w;
        }
        __syncthreads();
        rp[q][lq+0]=r0; rp[q][lq+1]=r1; rp[q][lq+2]=r2; rp[q][lq+3]=r3;
        __syncthreads();
        if (t < 48){
            float s = 0.f;
            #pragma unroll 8
            for (int qq = 0; qq < 32; qq++) s += rp[qq][t];
            g_rowsum[(b*N_+i)*L_ + t] = s;
            tsacc[t] += s;
            const float dv = xr[(size_t)i*L_ + t];
            g_diag[(b*N_+i)*L_ + t] = dv;
            tracc[t] += dv;
        }
    }
    __syncthreads();
    #pragma unroll
    for (int jj = 0; jj < 8; jj++){
        const int j = q + 32*jj;
        float* cp = g_colpart + ((size_t)((b*NSTRIP+istrip)*N_ + j))*L_ + lq;
        cp[0]=ca[jj][0]; cp[1]=ca[jj][1]; cp[2]=ca[jj][2]; cp[3]=ca[jj][3];
    }
    if (t < 48){
        g_stripT[(b*NSTRIP+istrip)*L_ + t] = tracc[t];
        g_stripS[(b*NSTRIP+istrip)*L_ + t] = tsacc[t];
    }
}

// ================= K1: per-node projections (8 nodes/block) + scalars =================
__global__ __launch_bounds__(96) void k_node(const float* __restrict__ w){
    const int b = blockIdx.y;
    const int n0 = blockIdx.x * 8;
    const int t = threadIdx.x;

    __shared__ float d_[8][48], r_[8][48], c_[8][48];
    __shared__ float tr[48], ts[48];

    for (int idx = t; idx < 8*48; idx += 96){
        const int nn = idx / 48, l = idx % 48;
        const int base = (b*N_ + n0 + nn)*L_ + l;
        d_[nn][l] = g_diag  [base];
        r_[nn][l] = g_rowsum[base];
        float s = 0.f;
        #pragma unroll
        for (int st = 0; st < NSTRIP; st++)
            s += g_colpart[((size_t)((b*NSTRIP+st)*N_ + n0 + nn))*L_ + l];
        c_[nn][l] = s;
    }
    if (t < 48){
        float a = 0.f, s = 0.f;
        #pragma unroll
        for (int st = 0; st < NSTRIP; st++){
            a += g_stripT[(b*NSTRIP+st)*L_ + t];
            s += g_stripS[(b*NSTRIP+st)*L_ + t];
        }
        tr[t] = a; ts[t] = s;
    }
    __syncthreads();

    float aA[8], aJ[8], aI[8];
    #pragma unroll
    for (int nn = 0; nn < 8; nn++){ aA[nn]=0.f; aJ[nn]=0.f; aI[nn]=0.f; }
    float ds = 0.f, sc = 0.f;

    for (int l = 0; l < 48; l++){
        const float* wl = w + l*F_ + t;
        const float w0  = __ldg(wl);
        const float w1  = __ldg(wl +    LF);
        const float w2  = __ldg(wl +  2*LF);
        const float w3  = __ldg(wl +  3*LF);
        const float w4  = __ldg(wl +  4*LF);
        const float w5  = __ldg(wl +  5*LF);
        const float w6  = __ldg(wl +  6*LF);
        const float w7  = __ldg(wl +  7*LF);
        const float w8  = __ldg(wl +  8*LF);
        const float w9  = __ldg(wl +  9*LF);
        const float w10 = __ldg(wl + 10*LF);
        const float w13 = __ldg(wl + 13*LF);
        const float w14 = __ldg(wl + 14*LF);
        const float trl = tr[l], tsl = ts[l];
        ds += trl*w3  + tsl*w4;
        sc += trl*w13 + tsl*w14;
        #pragma unroll
        for (int nn = 0; nn < 8; nn++){
            const float dd = d_[nn][l], rr = r_[nn][l], cc = c_[nn][l];
            aA[nn] += dd*w0 + rr*w1 + cc*w2;
            aJ[nn] += dd*w5 + rr*w6 + cc*w7;
            aI[nn] += dd*w8 + rr*w9 + cc*w10;
        }
    }
    #pragma unroll
    for (int nn = 0; nn < 8; nn++){
        const int o = (b*N_ + n0 + nn)*F_ + t;
        g_diagA[o] = aA[nn] + ds;
        g_bjs  [o] = aJ[nn] + sc;
        g_bi   [o] = aI[nn];
    }
}

// ================= K2: main fused kernel =================
// 16x16 (i,j) tile, 256 threads. FEATURE-pair FFMA2 packing:
//   acc holds {f, f+1}; w pairs come free as float2 of the w row (no
//   duplication); x broadcast {x,x} via 1 mov, reused across 6 f-pairs.
//   8 positions x 12 features per thread -> 1.67 B smem / FFMA2.
__global__ __launch_bounds__(256, 1)
void k_main(const float* __restrict__ x, const float* __restrict__ w,
            float* __restrict__ out){
    const int jt = blockIdx.x, it = blockIdx.y, b = blockIdx.z;
    const int i0 = it*16, j0 = jt*16;
    const int tid = threadIdx.x;

    extern __shared__ float sm[];
    float* xd    = sm;                 // [48][XS]
    float* xt    = xd + 48*XS;         // [48][XS]
    float* w12s  = xt + 48*XS;         // [48][96]
    float* w11s  = w12s + 48*96;       // [48][96]
    float* bis   = w11s + 48*96;       // [16][96]
    float* bjs_s = bis + 16*96;        // [16][96]

    // ---- stage w11 / w12 (plain copies) ----
    const float* w11g = w + 11*LF;
    const float* w12g = w + 12*LF;
    for (int idx = tid; idx < LF; idx += 256){
        w12s[idx] = __ldg(w12g + idx);
        w11s[idx] = __ldg(w11g + idx);
    }
    // ---- stage bi / bjs tiles ----
    for (int idx = tid; idx < 16*F_; idx += 256){
        const int r = idx / F_, f = idx % F_;
        bis  [idx] = g_bi [(b*N_ + i0 + r)*F_ + f];
        bjs_s[idx] = g_bjs[(b*N_ + j0 + r)*F_ + f];
    }
    // ---- stage x tiles (direct + transposed), [l][pos] layout ----
    const float* xb = x + ((size_t)b)*N_*N_*L_;
    for (int idx4 = tid; idx4 < 3072; idx4 += 256){
        const int ti  = idx4 / 192;
        const int rem = idx4 % 192;
        const int tj  = rem / 12;
        const int l4  = (rem % 12)*4;
        float4 v = *(const float4*)(xb + (size_t)(i0+ti)*N_*L_ + (size_t)(j0+tj)*L_ + l4);
        const int p = ti*16 + tj;
        xd[(l4+0)*XS + p] = v.x; xd[(l4+1)*XS + p] = v.y;
        xd[(l4+2)*XS + p] = v.z; xd[(l4+3)*XS + p] = v.w;
    }
    for (int idx4 = tid; idx4 < 3072; idx4 += 256){
        const int tj  = idx4 / 192;
        const int rem = idx4 % 192;
        const int ti  = rem / 12;
        const int l4  = (rem % 12)*4;
        float4 v = *(const float4*)(xb + (size_t)(j0+tj)*N_*L_ + (size_t)(i0+ti)*L_ + l4);
        const int p = ti*16 + tj;
        xt[(l4+0)*XS + p] = v.x; xt[(l4+1)*XS + p] = v.y;
        xt[(l4+2)*XS + p] = v.z; xt[(l4+3)*XS + p] = v.w;
    }
    __syncthreads();

    // ---- compute: 8 positions x 12 features (6 f-pairs) per thread ----
    const int fg  = tid & 7;          // 8 feature groups of 12
    const int pg  = tid >> 3;         // 32 groups of 8 positions
    const int f0  = fg * 12;
    const int ti  = pg >> 1;
    const int tjb = (pg & 1) * 8;
    const int p0  = ti*16 + tjb;

    ull acc[48];                      // [pos][fpair], fpair = {f, f+1}
    #pragma unroll
    for (int q = 0; q < 48; q++) acc[q] = 0ULL;

    const float* xdp = xd + p0;
    const float* xtp = xt + p0;
    const ull*   w2p = (const ull*)(w12s + f0);   // row stride 48 ull
    const ull*   w1p = (const ull*)(w11s + f0);

    for (int l = 0; l < 48; l++){
        const float4 a0 = *(const float4*)(xdp + l*XS);
        const float4 a1 = *(const float4*)(xdp + l*XS + 4);
        const float4 c0 = *(const float4*)(xtp + l*XS);
        const float4 c1 = *(const float4*)(xtp + l*XS + 4);
        ull w2[6], w1[6];
        #pragma unroll
        for (int k = 0; k < 6; k++){
            w2[k] = w2p[l*48 + k];
            w1[k] = w1p[l*48 + k];
        }
        const float xa[8] = {a0.x,a0.y,a0.z,a0.w,a1.x,a1.y,a1.z,a1.w};
        const float xc[8] = {c0.x,c0.y,c0.z,c0.w,c1.x,c1.y,c1.z,c1.w};
        #pragma unroll
        for (int p = 0; p < 8; p++){
            const ull da = pk2(xa[p]);
            const ull db = pk2(xc[p]);
            #pragma unroll
            for (int k = 0; k < 6; k++){
                acc[p*6+k] = ffma2(da, w2[k], acc[p*6+k]);
                acc[p*6+k] = ffma2(db, w1[k], acc[p*6+k]);
            }
        }
    }

    // ---- epilogue (feature pairs are contiguous in output) ----
    const int gi = i0 + ti;
    float bic[12];
    {
        const float4* bp = (const float4*)(bis + ti*F_ + f0);
        float4 b0 = bp[0], b1 = bp[1], b2 = bp[2];
        bic[0]=b0.x; bic[1]=b0.y; bic[2]=b0.z; bic[3]=b0.w;
        bic[4]=b1.x; bic[5]=b1.y; bic[6]=b1.z; bic[7]=b1.w;
        bic[8]=b2.x; bic[9]=b2.y; bic[10]=b2.z; bic[11]=b2.w;
    }
    float* orow = out + (((size_t)(b*N_ + gi))*N_ + j0)*F_ + f0;

    #pragma unroll
    for (int p = 0; p < 8; p++){
        const int tj = tjb + p;
        float v[12];
        #pragma unroll
        for (int k = 0; k < 6; k++) upk(acc[p*6+k], v[2*k], v[2*k+1]);
        const float* jp = bjs_s + tj*F_ + f0;
        #pragma unroll
        for (int f = 0; f < 12; f++) v[f] += bic[f] + jp[f];
        if (gi == j0 + tj){
            const float* dp = g_diagA + (size_t)(b*N_ + gi)*F_ + f0;
            #pragma unroll
            for (int f = 0; f < 12; f++) v[f] += __ldg(dp + f);
        }
        float* op = orow + (size_t)tj*F_;
        *(float4*)(op    ) = make_float4(v[0], v[1], v[2],  v[3]);
        *(float4*)(op + 4) = make_float4(v[4], v[5], v[6],  v[7]);
        *(float4*)(op + 8) = make_float4(v[8], v[9], v[10], v[11]);
    }
}

// ---------------- launch ----------------
extern "C" void kernel_launch(void* const* d_in, const int* in_sizes, int n_in,
                              void* d_out, int out_size){
    const float* x = (const float*)d_in[0];
    const float* w = (const float*)d_in[1];
    float* out = (float*)d_out;
    (void)in_sizes; (void)n_in; (void)out_size;

    k_reduce<<<dim3(NSTRIP, B_), 384>>>(x);
    k_node  <<<dim3(32, B_), 96>>>(w);

    const size_t smem = (size_t)(2*48*XS + 2*48*96 + 2*16*96) * sizeof(float); // 148992 B
    cudaFuncSetAttribute(k_main, cudaFuncAttributeMaxDynamicSharedMemorySize, (int)smem);
    k_main<<<dim3(16, 16, B_), 256, smem>>>(x, w, out);
}

// round 6
// speedup vs baseline: 1.9468x; 1.7228x over previous
#include <cuda_runtime.h>
#include <cstdint>

#define B_ 8
#define N_ 256
#define L_ 48
#define F_ 96
#define LF (L_*F_)
#define NSTRIP 32 // i-strips for k_reduce (8 rows each)

#define ASTR 100  // A smem row stride (floats): banks 4g+t bijective
#define BSTR 104  // B smem row stride (floats): banks 8t+g bijective

// ---------------- scratch (no allocation allowed) ----------------
__device__ float g_rowsum [B_*N_*L_];
__device__ float g_diag   [B_*N_*L_];
__device__ float g_colpart[B_*NSTRIP*N_*L_];
__device__ float g_stripT [B_*NSTRIP*L_];
__device__ float g_stripS [B_*NSTRIP*L_];
__device__ float g_diagA  [B_*N_*F_];
__device__ float g_bi     [B_*N_*F_];
__device__ float g_bjs    [B_*N_*F_];

// ---------------- tf32 helpers ----------------
__device__ __forceinline__ float tf32r(float v){
    uint32_t r; asm("cvt.rna.tf32.f32 %0, %1;" : "=r"(r) : "f"(v));
    return __uint_as_float(r);
}
__device__ __forceinline__ void mma_tf32(float* c, const uint32_t* a, const uint32_t* b){
    asm volatile(
        "mma.sync.aligned.m16n8k8.row.col.f32.tf32.tf32.f32 "
        "{%0,%1,%2,%3}, {%4,%5,%6,%7}, {%8,%9}, {%0,%1,%2,%3};"
        : "+f"(c[0]), "+f"(c[1]), "+f"(c[2]), "+f"(c[3])
        : "r"(a[0]), "r"(a[1]), "r"(a[2]), "r"(a[3]), "r"(b[0]), "r"(b[1]));
}

// ================= K0: fused reductions, one pass over x =================
__global__ __launch_bounds__(384) void k_reduce(const float* __restrict__ x){
    const int istrip = blockIdx.x, b = blockIdx.y;
    const int i0 = istrip*8;
    const int t = threadIdx.x;
    const int q = t/12, lq = (t%12)*4;

    __shared__ float rp[32][48];
    __shared__ float tracc[48], tsacc[48];
    if (t < 48){ tracc[t] = 0.f; tsacc[t] = 0.f; }

    float ca[8][4];
    #pragma unroll
    for (int jj = 0; jj < 8; jj++){ ca[jj][0]=0.f; ca[jj][1]=0.f; ca[jj][2]=0.f; ca[jj][3]=0.f; }

    const float* xb = x + ((size_t)b)*N_*N_*L_;

    for (int ii = 0; ii < 8; ii++){
        const int i = i0 + ii;
        const float* xr = xb + (size_t)i*N_*L_;
        float r0=0.f, r1=0.f, r2=0.f, r3=0.f;
        #pragma unroll
        for (int jj = 0; jj < 8; jj++){
            const int j = q + 32*jj;
            float4 v = *(const float4*)(xr + j*L_ + lq);
            ca[jj][0]+=v.x; ca[jj][1]+=v.y; ca[jj][2]+=v.z; ca[jj][3]+=v.w;
            r0+=v.x; r1+=v.y; r2+=v.z; r3+=v.w;
        }
        __syncthreads();
        rp[q][lq+0]=r0; rp[q][lq+1]=r1; rp[q][lq+2]=r2; rp[q][lq+3]=r3;
        __syncthreads();
        if (t < 48){
            float s = 0.f;
            #pragma unroll 8
            for (int qq = 0; qq < 32; qq++) s += rp[qq][t];
            g_rowsum[(b*N_+i)*L_ + t] = s;
            tsacc[t] += s;
            const float dv = xr[(size_t)i*L_ + t];
            g_diag[(b*N_+i)*L_ + t] = dv;
            tracc[t] += dv;
        }
    }
    __syncthreads();
    #pragma unroll
    for (int jj = 0; jj < 8; jj++){
        const int j = q + 32*jj;
        float* cp = g_colpart + ((size_t)((b*NSTRIP+istrip)*N_ + j))*L_ + lq;
        cp[0]=ca[jj][0]; cp[1]=ca[jj][1]; cp[2]=ca[jj][2]; cp[3]=ca[jj][3];
    }
    if (t < 48){
        g_stripT[(b*NSTRIP+istrip)*L_ + t] = tracc[t];
        g_stripS[(b*NSTRIP+istrip)*L_ + t] = tsacc[t];
    }
}

// ================= K1: per-node projections (8 nodes/block) + scalars =================
__global__ __launch_bounds__(96) void k_node(const float* __restrict__ w){
    const int b = blockIdx.y;
    const int n0 = blockIdx.x * 8;
    const int t = threadIdx.x;

    __shared__ float d_[8][48], r_[8][48], c_[8][48];
    __shared__ float tr[48], ts[48];

    for (int idx = t; idx < 8*48; idx += 96){
        const int nn = idx / 48, l = idx % 48;
        const int base = (b*N_ + n0 + nn)*L_ + l;
        d_[nn][l] = g_diag  [base];
        r_[nn][l] = g_rowsum[base];
        float s = 0.f;
        #pragma unroll
        for (int st = 0; st < NSTRIP; st++)
            s += g_colpart[((size_t)((b*NSTRIP+st)*N_ + n0 + nn))*L_ + l];
        c_[nn][l] = s;
    }
    if (t < 48){
        float a = 0.f, s = 0.f;
        #pragma unroll
        for (int st = 0; st < NSTRIP; st++){
            a += g_stripT[(b*NSTRIP+st)*L_ + t];
            s += g_stripS[(b*NSTRIP+st)*L_ + t];
        }
        tr[t] = a; ts[t] = s;
    }
    __syncthreads();

    float aA[8], aJ[8], aI[8];
    #pragma unroll
    for (int nn = 0; nn < 8; nn++){ aA[nn]=0.f; aJ[nn]=0.f; aI[nn]=0.f; }
    float ds = 0.f, sc = 0.f;

    for (int l = 0; l < 48; l++){
        const float* wl = w + l*F_ + t;
        const float w0  = __ldg(wl);
        const float w1  = __ldg(wl +    LF);
        const float w2  = __ldg(wl +  2*LF);
        const float w3  = __ldg(wl +  3*LF);
        const float w4  = __ldg(wl +  4*LF);
        const float w5  = __ldg(wl +  5*LF);
        const float w6  = __ldg(wl +  6*LF);
        const float w7  = __ldg(wl +  7*LF);
        const float w8  = __ldg(wl +  8*LF);
        const float w9  = __ldg(wl +  9*LF);
        const float w10 = __ldg(wl + 10*LF);
        const float w13 = __ldg(wl + 13*LF);
        const float w14 = __ldg(wl + 14*LF);
        const float trl = tr[l], tsl = ts[l];
        ds += trl*w3  + tsl*w4;
        sc += trl*w13 + tsl*w14;
        #pragma unroll
        for (int nn = 0; nn < 8; nn++){
            const float dd = d_[nn][l], rr = r_[nn][l], cc = c_[nn][l];
            aA[nn] += dd*w0 + rr*w1 + cc*w2;
            aJ[nn] += dd*w5 + rr*w6 + cc*w7;
            aI[nn] += dd*w8 + rr*w9 + cc*w10;
        }
    }
    #pragma unroll
    for (int nn = 0; nn < 8; nn++){
        const int o = (b*N_ + n0 + nn)*F_ + t;
        g_diagA[o] = aA[nn] + ds;
        g_bjs  [o] = aJ[nn] + sc;
        g_bi   [o] = aI[nn];
    }
}

// ================= K2: main kernel — tf32 mma.sync GEMM =================
// Per block: 16x16 (i,j) tile -> M=256 positions, N=96, K=96.
//   A[p][k] = x[b,i,j,k] (k<48) | x[b,j,i,k-48]; B[k][f] = w12|w11.
// 512 threads = 16 warps; warp (mw,nw): M=32 rows at mw*32, N=48 at nw*48.
__global__ __launch_bounds__(512, 1)
void k_main(const float* __restrict__ x, const float* __restrict__ w,
            float* __restrict__ out){
    const int jt = blockIdx.x, it = blockIdx.y, b = blockIdx.z;
    const int i0 = it*16, j0 = jt*16;
    const int tid = threadIdx.x;

    extern __shared__ float sm[];
    float* As    = sm;                 // [256][ASTR]
    float* Bs    = As + 256*ASTR;      // [96][BSTR]
    float* bis   = Bs + 96*BSTR;       // [16][96]
    float* bjs_s = bis + 16*96;        // [16][96]

    const float* xb = x + ((size_t)b)*N_*N_*L_;

    // ---- stage A direct half (k < 48) ----
    for (int idx = tid; idx < 256*12; idx += 512){
        const int p = idx / 12, k4 = (idx % 12)*4;
        const int ti = p >> 4, tj = p & 15;
        float4 v = *(const float4*)(xb + ((size_t)(i0+ti)*N_ + (j0+tj))*L_ + k4);
        float* dst = As + p*ASTR + k4;
        dst[0]=tf32r(v.x); dst[1]=tf32r(v.y); dst[2]=tf32r(v.z); dst[3]=tf32r(v.w);
    }
    // ---- stage A transposed half (k >= 48) ----
    for (int idx = tid; idx < 256*12; idx += 512){
        const int p = idx / 12, k4 = (idx % 12)*4;
        const int ti = p >> 4, tj = p & 15;
        float4 v = *(const float4*)(xb + ((size_t)(j0+tj)*N_ + (i0+ti))*L_ + k4);
        float* dst = As + p*ASTR + 48 + k4;
        dst[0]=tf32r(v.x); dst[1]=tf32r(v.y); dst[2]=tf32r(v.z); dst[3]=tf32r(v.w);
    }
    // ---- stage B = [w12 ; w11] ----
    {
        const float* w12g = w + 12*LF;
        const float* w11g = w + 11*LF;
        for (int idx = tid; idx < 96*24; idx += 512){
            const int k = idx / 24, f4 = (idx % 24)*4;
            const float* src = (k < 48) ? (w12g + k*F_ + f4) : (w11g + (k-48)*F_ + f4);
            float4 v = *(const float4*)src;
            float* dst = Bs + k*BSTR + f4;
            dst[0]=tf32r(v.x); dst[1]=tf32r(v.y); dst[2]=tf32r(v.z); dst[3]=tf32r(v.w);
        }
    }
    // ---- stage bias tiles ----
    for (int idx = tid; idx < 16*F_; idx += 512){
        const int r = idx / F_, f = idx % F_;
        bis  [idx] = g_bi [(b*N_ + i0 + r)*F_ + f];
        bjs_s[idx] = g_bjs[(b*N_ + j0 + r)*F_ + f];
    }
    __syncthreads();

    // ---- warp mapping ----
    const int wid = tid >> 5, lane = tid & 31;
    const int mw = wid >> 1, nw = wid & 1;
    const int g = lane >> 2, t = lane & 3;
    const int mb = mw*32, nb = nw*48;

    float acc[2][6][4];
    #pragma unroll
    for (int fm = 0; fm < 2; fm++)
        #pragma unroll
        for (int tl = 0; tl < 6; tl++)
            #pragma unroll
            for (int q = 0; q < 4; q++) acc[fm][tl][q] = 0.f;

    const float* A0 = As + (mb + g)*ASTR + t;      // fm=0 a0
    const float* B0 = Bs + t*BSTR + nb + g;        // b0 tile0

    #pragma unroll 4
    for (int ks = 0; ks < 12; ks++){
        const int k0 = ks*8;
        uint32_t a[2][4];
        #pragma unroll
        for (int fm = 0; fm < 2; fm++){
            const float* ap = A0 + fm*16*ASTR + k0;
            a[fm][0] = __float_as_uint(ap[0]);
            a[fm][1] = __float_as_uint(ap[8*ASTR]);
            a[fm][2] = __float_as_uint(ap[4]);
            a[fm][3] = __float_as_uint(ap[8*ASTR + 4]);
        }
        const float* bp = B0 + k0*BSTR;
        uint32_t bfr[6][2];
        #pragma unroll
        for (int tl = 0; tl < 6; tl++){
            bfr[tl][0] = __float_as_uint(bp[tl*8]);
            bfr[tl][1] = __float_as_uint(bp[4*BSTR + tl*8]);
        }
        #pragma unroll
        for (int fm = 0; fm < 2; fm++)
            #pragma unroll
            for (int tl = 0; tl < 6; tl++)
                mma_tf32(acc[fm][tl], a[fm], bfr[tl]);
    }

    // ---- epilogue ----
    #pragma unroll
    for (int fm = 0; fm < 2; fm++){
        const int ti_l = mw*2 + fm;
        const int gi = i0 + ti_l;
        const float* irow = bis + ti_l*F_;
        const float* drow = g_diagA + ((size_t)(b*N_ + gi))*F_;
        #pragma unroll
        for (int half = 0; half < 2; half++){
            const int tj = g + half*8;
            const bool dg = (ti_l == tj) && (it == jt);
            float* orow = out + (((size_t)(b*N_ + gi))*N_ + (j0 + tj))*F_;
            const float* jrow = bjs_s + tj*F_;
            #pragma unroll
            for (int tl = 0; tl < 6; tl++){
                const int f = nb + tl*8 + 2*t;
                float v0 = acc[fm][tl][half*2+0] + irow[f]   + jrow[f];
                float v1 = acc[fm][tl][half*2+1] + irow[f+1] + jrow[f+1];
                if (dg){ v0 += __ldg(drow + f); v1 += __ldg(drow + f + 1); }
                *(float2*)(orow + f) = make_float2(v0, v1);
            }
        }
    }
}

// ---------------- launch ----------------
extern "C" void kernel_launch(void* const* d_in, const int* in_sizes, int n_in,
                              void* d_out, int out_size){
    const float* x = (const float*)d_in[0];
    const float* w = (const float*)d_in[1];
    float* out = (float*)d_out;
    (void)in_sizes; (void)n_in; (void)out_size;

    k_reduce<<<dim3(NSTRIP, B_), 384>>>(x);
    k_node  <<<dim3(32, B_), 96>>>(w);

    const size_t smem = (size_t)(256*ASTR + 96*BSTR + 2*16*96) * sizeof(float); // 154624 B
    cudaFuncSetAttribute(k_main, cudaFuncAttributeMaxDynamicSharedMemorySize, (int)smem);
    k_main<<<dim3(16, 16, B_), 512, smem>>>(x, w, out);
}